// round 6
// baseline (speedup 1.0000x reference)
#include <cuda_runtime.h>
#include <mma.h>
#include <cstdint>

using namespace nvcuda;

#define Bdim 8
#define Hdim 16
#define Sdim 4096
#define Ddim 64
#define Kdim 256
#define BH (Bdim * Hdim)

// Scratch: projected K (transposed [bh][d][kk]) and projected V ([bh][kk][d]).
__device__ float g_kprojT[(size_t)BH * Ddim * Kdim];
__device__ float g_vproj[(size_t)BH * Kdim * Ddim];

// ---------------------------------------------------------------------------
// Stage A: per bh, for which in {k,v}:
//   C[kk=256, d=64] = sum_n proj[n,kk] * (in[bh,n,d] * mask[b,n])
// WMMA tf32 m16n16k8 with 3xTF32 split (hi/lo) => ~fp32 accuracy.
// Block: 256 threads (8 warps), tile M=256 x N=64, K-chunk 32.
// A (proj chunk) stored [n][kk] -> used col_major; B (kv chunk) [n][d] row_major.
// grid = (BH). One wave of 128 blocks.
// ---------------------------------------------------------------------------
#define AS_LD 260          // 32 x 260 floats per copy (hi, lo)
#define BS_LD 68           // 32 x 68 floats per copy
#define ST_LD 68           // 256 x 68 stage for epilogue (reuses A area)
#define PROJ_SMEM_FLOATS (2 * 32 * AS_LD + 2 * 32 * BS_LD)
#define PROJ_SMEM_BYTES (PROJ_SMEM_FLOATS * 4)

__global__ __launch_bounds__(256) void kv_proj_wmma(
    const float* __restrict__ kin, const float* __restrict__ vin,
    const float* __restrict__ pk, const float* __restrict__ pv,
    const float* __restrict__ mask)
{
    extern __shared__ float sm[];
    float* as_hi = sm;                       // 32 x AS_LD
    float* as_lo = sm + 32 * AS_LD;
    float* bs_hi = sm + 64 * AS_LD;          // 32 x BS_LD
    float* bs_lo = bs_hi + 32 * BS_LD;
    float* stage = sm;                       // 256 x ST_LD (epilogue reuse)

    const int bh = blockIdx.x;
    const int b  = bh >> 4;                  // H = 16
    const int t  = threadIdx.x;
    const int wid = t >> 5;
    const int warp_m = wid & 3;              // 4 M-groups of 64 rows
    const int warp_n = wid >> 2;             // 2 N-groups of 32 cols
    const int m0  = warp_m * 64;
    const int n0c = warp_n * 32;

    const float* mk = mask + (size_t)b * Sdim;

    for (int which = 0; which < 2; which++) {
        const float* Ag = which ? pv : pk;                       // [S, 256]
        const float* Bg = (which ? vin : kin) + (size_t)bh * Sdim * Ddim;

        wmma::fragment<wmma::accumulator, 16, 16, 8, float> acc[4][2];
#pragma unroll
        for (int mi = 0; mi < 4; mi++)
#pragma unroll
            for (int ni = 0; ni < 2; ni++)
                wmma::fill_fragment(acc[mi][ni], 0.0f);

        // register-staged prefetch of chunk 0
        float4 pa[8]; float4 pbv[2]; float pm[2];
#pragma unroll
        for (int l = 0; l < 8; l++) {
            int idx = t + l * 256; int n = idx >> 6, k4 = idx & 63;
            pa[l] = *(const float4*)&Ag[(size_t)n * Kdim + k4 * 4];
        }
#pragma unroll
        for (int l = 0; l < 2; l++) {
            int idx = t + l * 256; int n = idx >> 4, d4 = idx & 15;
            pm[l]  = mk[n];
            pbv[l] = *(const float4*)&Bg[(size_t)n * Ddim + d4 * 4];
        }

        for (int i = 0; i < Sdim / 32; i++) {
            __syncthreads();   // previous chunk's MMAs done before overwrite
            // ---- STS with tf32 hi/lo split ----
#pragma unroll
            for (int l = 0; l < 8; l++) {
                int idx = t + l * 256; int n = idx >> 6, k4 = idx & 63;
                float4 v = pa[l];
                float4 h, lo;
                h.x = wmma::__float_to_tf32(v.x); lo.x = wmma::__float_to_tf32(v.x - h.x);
                h.y = wmma::__float_to_tf32(v.y); lo.y = wmma::__float_to_tf32(v.y - h.y);
                h.z = wmma::__float_to_tf32(v.z); lo.z = wmma::__float_to_tf32(v.z - h.z);
                h.w = wmma::__float_to_tf32(v.w); lo.w = wmma::__float_to_tf32(v.w - h.w);
                *(float4*)&as_hi[n * AS_LD + k4 * 4] = h;
                *(float4*)&as_lo[n * AS_LD + k4 * 4] = lo;
            }
#pragma unroll
            for (int l = 0; l < 2; l++) {
                int idx = t + l * 256; int n = idx >> 4, d4 = idx & 15;
                float m = pm[l];
                float4 v = pbv[l];
                v.x *= m; v.y *= m; v.z *= m; v.w *= m;
                float4 h, lo;
                h.x = wmma::__float_to_tf32(v.x); lo.x = wmma::__float_to_tf32(v.x - h.x);
                h.y = wmma::__float_to_tf32(v.y); lo.y = wmma::__float_to_tf32(v.y - h.y);
                h.z = wmma::__float_to_tf32(v.z); lo.z = wmma::__float_to_tf32(v.z - h.z);
                h.w = wmma::__float_to_tf32(v.w); lo.w = wmma::__float_to_tf32(v.w - h.w);
                *(float4*)&bs_hi[n * BS_LD + d4 * 4] = h;
                *(float4*)&bs_lo[n * BS_LD + d4 * 4] = lo;
            }
            __syncthreads();

            // prefetch next chunk (overlaps LDG latency with MMA below)
            if (i < Sdim / 32 - 1) {
                const int n0 = (i + 1) * 32;
#pragma unroll
                for (int l = 0; l < 8; l++) {
                    int idx = t + l * 256; int n = idx >> 6, k4 = idx & 63;
                    pa[l] = *(const float4*)&Ag[(size_t)(n0 + n) * Kdim + k4 * 4];
                }
#pragma unroll
                for (int l = 0; l < 2; l++) {
                    int idx = t + l * 256; int n = idx >> 4, d4 = idx & 15;
                    pm[l]  = mk[n0 + n];
                    pbv[l] = *(const float4*)&Bg[(size_t)(n0 + n) * Ddim + d4 * 4];
                }
            }

            // ---- MMA: 4 k-steps of 8 ----
#pragma unroll
            for (int s = 0; s < 4; s++) {
                wmma::fragment<wmma::matrix_a, 16, 16, 8, wmma::precision::tf32,
                               wmma::col_major> ah[4], al[4];
                wmma::fragment<wmma::matrix_b, 16, 16, 8, wmma::precision::tf32,
                               wmma::row_major> bh4[2], bl4[2];
#pragma unroll
                for (int mi = 0; mi < 4; mi++) {
                    wmma::load_matrix_sync(ah[mi], as_hi + s * 8 * AS_LD + m0 + mi * 16, AS_LD);
                    wmma::load_matrix_sync(al[mi], as_lo + s * 8 * AS_LD + m0 + mi * 16, AS_LD);
                }
#pragma unroll
                for (int ni = 0; ni < 2; ni++) {
                    wmma::load_matrix_sync(bh4[ni], bs_hi + s * 8 * BS_LD + n0c + ni * 16, BS_LD);
                    wmma::load_matrix_sync(bl4[ni], bs_lo + s * 8 * BS_LD + n0c + ni * 16, BS_LD);
                }
#pragma unroll
                for (int mi = 0; mi < 4; mi++)
#pragma unroll
                    for (int ni = 0; ni < 2; ni++) {
                        wmma::mma_sync(acc[mi][ni], ah[mi], bl4[ni], acc[mi][ni]);
                        wmma::mma_sync(acc[mi][ni], al[mi], bh4[ni], acc[mi][ni]);
                        wmma::mma_sync(acc[mi][ni], ah[mi], bh4[ni], acc[mi][ni]);
                    }
            }
        }

        // ---- epilogue: stage C [256 x 64] in smem, then layout-specific write ----
        __syncthreads();
#pragma unroll
        for (int mi = 0; mi < 4; mi++)
#pragma unroll
            for (int ni = 0; ni < 2; ni++)
                wmma::store_matrix_sync(stage + (size_t)(m0 + mi * 16) * ST_LD + n0c + ni * 16,
                                        acc[mi][ni], ST_LD, wmma::mem_row_major);
        __syncthreads();

        if (which == 0) {
            float* dst = g_kprojT + (size_t)bh * Ddim * Kdim;    // [d][kk]
#pragma unroll
            for (int l = 0; l < 16; l++) {
                int v4i = t + l * 256;
                int d = v4i >> 6, kq = v4i & 63;
                float4 o;
                o.x = stage[(size_t)(kq * 4 + 0) * ST_LD + d];
                o.y = stage[(size_t)(kq * 4 + 1) * ST_LD + d];
                o.z = stage[(size_t)(kq * 4 + 2) * ST_LD + d];
                o.w = stage[(size_t)(kq * 4 + 3) * ST_LD + d];
                *(float4*)&dst[(size_t)d * Kdim + kq * 4] = o;
            }
        } else {
            float* dst = g_vproj + (size_t)bh * Kdim * Ddim;     // [kk][d]
#pragma unroll
            for (int l = 0; l < 16; l++) {
                int v4i = t + l * 256;
                int kk = v4i >> 4, d4 = v4i & 15;
                *(float4*)&dst[(size_t)kk * Ddim + d4 * 4] =
                    *(const float4*)&stage[(size_t)kk * ST_LD + d4 * 4];
            }
        }
        __syncthreads();
    }
}

// ---------------------------------------------------------------------------
// Kernel B: per (bh, 64-row q tile): scores -> softmax -> probs + out. fp32.
// 512 threads; kp [d][kk] + vp [kk][d] resident in SMEM; sc stride 260.
// ---------------------------------------------------------------------------
#define SC_STRIDE 260
#define QROWS 64
#define SMEM_B_BYTES ((QROWS * 64 + 64 * 256 + 256 * 64 + QROWS * SC_STRIDE) * 4)

__global__ __launch_bounds__(512) void attn_kernel(
    const float* __restrict__ q, float* __restrict__ out, float* __restrict__ probs)
{
    extern __shared__ float sm[];
    float* qs = sm;                        // 64 x 64
    float* kp = qs + QROWS * 64;           // 64 x 256  ([d][kk])
    float* vp = kp + 64 * 256;             // 256 x 64  ([kk][d])
    float* sc = vp + 256 * 64;             // 64 x SC_STRIDE

    const int bh = blockIdx.y;
    const int q0 = blockIdx.x * QROWS;
    const int t  = threadIdx.x;

    // ---- loads ----
    const float* qb = q + ((size_t)bh * Sdim + q0) * Ddim;
#pragma unroll
    for (int l = 0; l < 2; l++) {
        int idx = t + l * 512;
        *(float4*)&qs[idx * 4] = *(const float4*)&qb[(size_t)idx * 4];
    }
    const float* gk = g_kprojT + (size_t)bh * Kdim * Ddim;
    const float* gv = g_vproj  + (size_t)bh * Kdim * Ddim;
#pragma unroll
    for (int l = 0; l < 8; l++) {
        int idx = t + l * 512;
        *(float4*)&kp[idx * 4] = *(const float4*)&gk[(size_t)idx * 4];
        *(float4*)&vp[idx * 4] = *(const float4*)&gv[(size_t)idx * 4];
    }
    __syncthreads();

    // ---- scores: thread = 8 q-rows x 4 k-cols ----
    {
        const int qg = t >> 6;             // 0..7 -> rows qg*8..qg*8+7
        const int kt = t & 63;             // k group (float4)
        float acc[8][4];
#pragma unroll
        for (int r = 0; r < 8; r++)
#pragma unroll
            for (int j = 0; j < 4; j++) acc[r][j] = 0.0f;

        const float* kpp = kp + kt * 4;
        const float* qss = qs + qg * 8 * 64;
        for (int d = 0; d < 64; d++) {
            float4 kv = *(const float4*)&kpp[d * 256];
#pragma unroll
            for (int r = 0; r < 8; r++) {
                float qv = qss[r * 64 + d];
                acc[r][0] += qv * kv.x;
                acc[r][1] += qv * kv.y;
                acc[r][2] += qv * kv.z;
                acc[r][3] += qv * kv.w;
            }
        }
#pragma unroll
        for (int r = 0; r < 8; r++)
            *(float4*)&sc[(qg * 8 + r) * SC_STRIDE + kt * 4] =
                make_float4(acc[r][0] * 0.125f, acc[r][1] * 0.125f,
                            acc[r][2] * 0.125f, acc[r][3] * 0.125f);
    }
    __syncthreads();

    // ---- softmax: 8 lanes per row, 32 values each (64 rows x 512 threads) ----
    {
        const int row = t >> 3;
        const int seg = t & 7;
        float* base = sc + row * SC_STRIDE + seg * 32;
        float v[32];
#pragma unroll
        for (int i = 0; i < 8; i++) {
            float4 f = *(float4*)&base[i * 4];
            v[i * 4] = f.x; v[i * 4 + 1] = f.y; v[i * 4 + 2] = f.z; v[i * 4 + 3] = f.w;
        }
        float mx = -1e30f;
#pragma unroll
        for (int i = 0; i < 32; i++) mx = fmaxf(mx, v[i]);
#pragma unroll
        for (int o = 1; o < 8; o <<= 1)
            mx = fmaxf(mx, __shfl_xor_sync(0xffffffffu, mx, o));
        float sum = 0.0f;
#pragma unroll
        for (int i = 0; i < 32; i++) { v[i] = __expf(v[i] - mx); sum += v[i]; }
#pragma unroll
        for (int o = 1; o < 8; o <<= 1)
            sum += __shfl_xor_sync(0xffffffffu, sum, o);
        float inv = __fdividef(1.0f, sum);
#pragma unroll
        for (int i = 0; i < 8; i++)
            *(float4*)&base[i * 4] =
                make_float4(v[i * 4] * inv, v[i * 4 + 1] * inv,
                            v[i * 4 + 2] * inv, v[i * 4 + 3] * inv);
    }
    __syncthreads();

    if (t < 128) {
        // ---- out = probs @ v_proj : 128 threads, 8 q-rows x 4 d each ----
        const int rq0 = (t >> 4) * 8;      // 0,8,..,56
        const int dg  = t & 15;            // d group (float4)
        float acc[8][4];
#pragma unroll
        for (int r = 0; r < 8; r++)
#pragma unroll
            for (int j = 0; j < 4; j++) acc[r][j] = 0.0f;

        const float* vpp = vp + dg * 4;
        const float* scb = sc + rq0 * SC_STRIDE;
        for (int k = 0; k < 256; k++) {
            float4 v4 = *(const float4*)&vpp[k * 64];
#pragma unroll
            for (int r = 0; r < 8; r++) {
                float p = scb[r * SC_STRIDE + k];
                acc[r][0] += p * v4.x;
                acc[r][1] += p * v4.y;
                acc[r][2] += p * v4.z;
                acc[r][3] += p * v4.w;
            }
        }
        float* ob = out + ((size_t)bh * Sdim + q0) * Ddim;
#pragma unroll
        for (int r = 0; r < 8; r++)
            *(float4*)&ob[(size_t)(rq0 + r) * Ddim + dg * 4] =
                make_float4(acc[r][0], acc[r][1], acc[r][2], acc[r][3]);
    } else if (probs) {
        // ---- probs write: 384 threads, coalesced from SMEM ----
        float* pb = probs + ((size_t)bh * Sdim + q0) * Kdim;
        const int j = t - 128;
#pragma unroll
        for (int l = 0; l < 11; l++) {
            int v4i = j + l * 384;
            if (v4i < QROWS * 64) {
                int qq = v4i >> 6;
                int kc = v4i & 63;
                *(float4*)&pb[(size_t)qq * Kdim + kc * 4] =
                    *(const float4*)&sc[qq * SC_STRIDE + kc * 4];
            }
        }
    }
}

// ---------------------------------------------------------------------------
extern "C" void kernel_launch(void* const* d_in, const int* in_sizes, int n_in,
                              void* d_out, int out_size)
{
    const float* q    = (const float*)d_in[0];
    const float* k    = (const float*)d_in[1];
    const float* v    = (const float*)d_in[2];
    const float* mask = (const float*)d_in[3];
    const float* pk   = (const float*)d_in[4];
    const float* pv   = (const float*)d_in[5];

    float* out = (float*)d_out;
    const long OUT_ELEMS = (long)BH * Sdim * Ddim;   // 33,554,432
    float* probs = ((long)out_size > OUT_ELEMS) ? (out + OUT_ELEMS) : nullptr;

    cudaFuncSetAttribute(kv_proj_wmma, cudaFuncAttributeMaxDynamicSharedMemorySize,
                         PROJ_SMEM_BYTES);
    cudaFuncSetAttribute(attn_kernel, cudaFuncAttributeMaxDynamicSharedMemorySize,
                         SMEM_B_BYTES);

    // Stage A: tensor-core (legacy mma.sync tf32, 3xTF32 split) projection GEMMs
    kv_proj_wmma<<<BH, 256, PROJ_SMEM_BYTES>>>(k, v, pk, pv, mask);
    // Stage B: attention (fp32 SIMT)
    attn_kernel<<<dim3(Sdim / QROWS, BH), 512, SMEM_B_BYTES>>>(q, out, probs);
}